// round 15
// baseline (speedup 1.0000x reference)
#include <cuda_runtime.h>
#include <cuda_bf16.h>
#include <stdint.h>

// Problem constants
#define IN_F   64
#define OUT_F  32
#define NDIM   2080               // IN_F*OUT_F + OUT_F
#define TOKENS 16384              // B*S = 8*2048
#define MPAD   2176               // 17 * 128 (padded m-dim)
#define NTRI   (NDIM*(NDIM-1)/2)  // 2,162,160

// GEMM tiling
#define BM 128
#define BN 128
#define BK 32
#define NT 512                    // 16 warps: 4x4 warp grid, warp tile 32x32
#define JTILES 17                 // ceil(2080/128)

// Scratch (device globals: allocation-free at runtime)
__device__ __nv_bfloat16 g_E[(size_t)TOKENS * NDIM];  // eps in bf16, row-major [t][n]
__device__ __nv_bfloat16 g_A[(size_t)MPAD * NDIM];    // strict-lower cov in bf16, [m][n], diag=0, padded rows zero
__device__ float         g_d[NDIM];                   // exp(0.5*logvar)

// ---------------------------------------------------------------------------
// prep: diag scale
// ---------------------------------------------------------------------------
__global__ void k_scale(const float* __restrict__ logvar) {
    int i = blockIdx.x * blockDim.x + threadIdx.x;
    if (i < NDIM) g_d[i] = expf(0.5f * logvar[i]);
}

// ---------------------------------------------------------------------------
// prep: A matrix (strictly lower triangular cov, bf16, zero elsewhere)
// tril_indices(n,-1) row-major: index(m,n) = m*(m-1)/2 + n   (n < m)
// ---------------------------------------------------------------------------
__global__ void k_prepA(const float* __restrict__ cov) {
    int idx = blockIdx.x * blockDim.x + threadIdx.x;
    if (idx >= MPAD * NDIM) return;
    int m = idx / NDIM;
    int n = idx - m * NDIM;
    float v = 0.0f;
    if (m < NDIM && n < m) v = cov[m * (m - 1) / 2 + n];
    g_A[idx] = __float2bfloat16(v);
}

// ---------------------------------------------------------------------------
// prep: eps -> bf16, and exact fp32 base term written to out:
//   y_base[t,k] = loc[k] + d[k]*eps[t,k]
//              + sum_h x[t,h] * ( loc[32+32h+k] + d[32+32h+k]*eps[t,32+32h+k] )
// One warp per token; lane = k. Iteration i reads n = 32*i + lane:
//   i==0  -> bias term, i>=1 -> h = i-1 term. 65 iterations cover all 2080 n.
// ---------------------------------------------------------------------------
__global__ void k_prepE(const float* __restrict__ eps, const float* __restrict__ x,
                        const float* __restrict__ loc, float* __restrict__ out) {
    int warp = threadIdx.x >> 5;
    int lane = threadIdx.x & 31;
    int t = blockIdx.x * (blockDim.x >> 5) + warp;
    if (t >= TOKENS) return;

    const float* er = eps + (size_t)t * NDIM;
    __nv_bfloat16* eb = g_E + (size_t)t * NDIM;
    const float* xr = x + t * IN_F;

    float acc = 0.0f;
    for (int i = 0; i < 65; ++i) {
        int n = i * 32 + lane;
        float ep = er[n];
        eb[n] = __float2bfloat16(ep);
        float wv = loc[n] + g_d[n] * ep;
        acc = (i == 0) ? wv : fmaf(xr[i - 1], wv, acc);
    }
    out[t * OUT_F + lane] = acc;
}

// ---------------------------------------------------------------------------
// GEMM + fused epilogue
// ---------------------------------------------------------------------------
__device__ __forceinline__ void cpasync16(uint32_t d, const void* s) {
    asm volatile("cp.async.cg.shared.global [%0], [%1], 16;" :: "r"(d), "l"(s));
}
__device__ __forceinline__ void ldsm_x4(uint32_t& r0, uint32_t& r1, uint32_t& r2, uint32_t& r3, uint32_t a) {
    asm volatile("ldmatrix.sync.aligned.m8n8.x4.shared.b16 {%0,%1,%2,%3}, [%4];"
                 : "=r"(r0), "=r"(r1), "=r"(r2), "=r"(r3) : "r"(a));
}
__device__ __forceinline__ void ldsm_x2(uint32_t& r0, uint32_t& r1, uint32_t a) {
    asm volatile("ldmatrix.sync.aligned.m8n8.x2.shared.b16 {%0,%1}, [%2];"
                 : "=r"(r0), "=r"(r1) : "r"(a));
}
__device__ __forceinline__ void mma16816(float* c, const uint32_t* a, const uint32_t* b) {
    asm volatile("mma.sync.aligned.m16n8k16.row.col.f32.bf16.bf16.f32 "
                 "{%0,%1,%2,%3}, {%4,%5,%6,%7}, {%8,%9}, {%0,%1,%2,%3};"
                 : "+f"(c[0]), "+f"(c[1]), "+f"(c[2]), "+f"(c[3])
                 : "r"(a[0]), "r"(a[1]), "r"(a[2]), "r"(a[3]), "r"(b[0]), "r"(b[1]));
}

// smem layout (dynamic):
//   [0,8192)      E tile stage 0  (128 rows x 64B, XOR-swizzled 16B chunks)
//   [8192,16384)  E tile stage 1
//   [16384,24576) A tile stage 0
//   [24576,32768) A tile stage 1
//   [32768, +128*33*4) y accumulator (pitch 33 floats to dodge bank conflicts)
#define SMEM_Y_OFF 32768
#define SMEM_BYTES (SMEM_Y_OFF + 128 * 33 * 4)

__global__ void __launch_bounds__(NT, 1) k_gemm(const float* __restrict__ x,
                                                float* __restrict__ out) {
    extern __shared__ char smem[];
    uint32_t su = (uint32_t)__cvta_generic_to_shared(smem);
    float* ys = (float*)(smem + SMEM_Y_OFF);

    int tid  = threadIdx.x;
    int lane = tid & 31;
    int warp = tid >> 5;
    int wr = warp >> 2;   // token 32-block within CTA (0..3)
    int wc = warp & 3;    // m-col 32-block within CTA (0..3)

    int bj       = blockIdx.x % JTILES;       // m-tile (bid order: j fastest -> eps L2 reuse)
    int tokTile  = blockIdx.x / JTILES;
    int tok_base = tokTile * BM;
    int arow_base = bj * BN;
    int Ksteps = min(65, 4 * (bj + 1));       // triangular: n < 128*(bj+1), BK=32

    // zero y accumulator
    for (int i = tid; i < 128 * 33; i += NT) ys[i] = 0.0f;

    float acc[2][4][4];
    #pragma unroll
    for (int a = 0; a < 2; ++a)
        #pragma unroll
        for (int b = 0; b < 4; ++b)
            #pragma unroll
            for (int r = 0; r < 4; ++r) acc[a][b][r] = 0.0f;

    // cp.async task: each thread owns one 16B chunk of E tile and one of A tile
    int rr0 = tid >> 2, cc0 = tid & 3;
    uint32_t swz = ((uint32_t)(cc0 ^ ((rr0 >> 1) & 3))) << 4;
    uint32_t edst = su + rr0 * 64 + swz;
    uint32_t adst = su + 16384 + rr0 * 64 + swz;
    const __nv_bfloat16* esrc = g_E + (size_t)(tok_base + rr0) * NDIM + cc0 * 8;
    const __nv_bfloat16* asrc = g_A + (size_t)(arow_base + rr0) * NDIM + cc0 * 8;

    auto issue = [&](int st, int ks) {
        cpasync16(edst + st * 8192, esrc + ks * 32);
        cpasync16(adst + st * 8192, asrc + ks * 32);
        asm volatile("cp.async.commit_group;");
    };

    issue(0, 0);
    for (int ks = 0; ks < Ksteps; ++ks) {
        if (ks + 1 < Ksteps) {
            issue((ks + 1) & 1, ks + 1);
            asm volatile("cp.async.wait_group 1;");
        } else {
            asm volatile("cp.async.wait_group 0;");
        }
        __syncthreads();

        int st = ks & 1;
        uint32_t eBase = su + st * 8192;
        uint32_t aBase = su + 16384 + st * 8192;

        #pragma unroll
        for (int s = 0; s < 2; ++s) {          // two k16 halves of BK=32
            uint32_t a[2][4], b[4][2];
            #pragma unroll
            for (int fm = 0; fm < 2; ++fm) {   // A operand = E tile (tokens x k)
                int row = 32 * wr + 16 * fm + (lane & 7) + ((lane >> 3) & 1) * 8;
                int ch = 2 * s + (lane >> 4);
                uint32_t ad = eBase + row * 64 + (((uint32_t)(ch ^ ((row >> 1) & 3))) << 4);
                ldsm_x4(a[fm][0], a[fm][1], a[fm][2], a[fm][3], ad);
            }
            #pragma unroll
            for (int fn = 0; fn < 4; ++fn) {   // B operand = A tile (m x k), col-major fit
                int row = 32 * wc + 8 * fn + (lane & 7);
                int ch = 2 * s + ((lane >> 3) & 1);
                uint32_t ad = aBase + row * 64 + (((uint32_t)(ch ^ ((row >> 1) & 3))) << 4);
                ldsm_x2(b[fn][0], b[fn][1], ad);
            }
            #pragma unroll
            for (int fm = 0; fm < 2; ++fm)
                #pragma unroll
                for (int fn = 0; fn < 4; ++fn)
                    mma16816(acc[fm][fn], a[fm], b[fn]);
        }
        __syncthreads();
    }

    // Fused epilogue: C[t,m] contributes to exactly one k
    //   m < 32      : k = m,            weight 1      (bias)
    //   m >= 32     : k = (m-32)&31,    weight x[t, (m-32)>>5]
    #pragma unroll
    for (int fm = 0; fm < 2; ++fm) {
        #pragma unroll
        for (int fn = 0; fn < 4; ++fn) {
            #pragma unroll
            for (int r = 0; r < 4; ++r) {
                int tl = 32 * wr + 16 * fm + (lane >> 2) + (r >> 1) * 8;
                int ml = 32 * wc + 8 * fn + (lane & 3) * 2 + (r & 1);
                int m = arow_base + ml;
                if (m < NDIM) {
                    float w;
                    int k;
                    if (m < OUT_F) { w = 1.0f; k = m; }
                    else {
                        int mm = m - OUT_F;
                        k = mm & 31;
                        w = x[(tok_base + tl) * IN_F + (mm >> 5)];
                    }
                    atomicAdd(&ys[tl * 33 + k], w * acc[fm][fn][r]);
                }
            }
        }
    }
    __syncthreads();

    for (int i = tid; i < BM * OUT_F; i += NT) {
        int tl = i >> 5, k = i & 31;
        atomicAdd(&out[(size_t)(tok_base + tl) * OUT_F + k], ys[tl * 33 + k]);
    }
}

// ---------------------------------------------------------------------------
// launch
// ---------------------------------------------------------------------------
extern "C" void kernel_launch(void* const* d_in, const int* in_sizes, int n_in,
                              void* d_out, int out_size) {
    const float *x = nullptr, *eps = nullptr, *loc = nullptr, *logvar = nullptr, *cov = nullptr;
    for (int i = 0; i < n_in; ++i) {
        int s = in_sizes[i];
        const float* p = (const float*)d_in[i];
        if (s == TOKENS * IN_F)      x = p;
        else if (s == TOKENS * NDIM) eps = p;
        else if (s == NTRI)          cov = p;
        else if (s == NDIM) { if (!loc) loc = p; else logvar = p; }  // dict order: loc, logvar
    }
    if (!x || !eps || !loc || !logvar || !cov) return;
    float* out = (float*)d_out;

    cudaFuncSetAttribute(k_gemm, cudaFuncAttributeMaxDynamicSharedMemorySize, SMEM_BYTES);

    k_scale<<<(NDIM + 255) / 256, 256>>>(logvar);
    k_prepA<<<(MPAD * NDIM + 255) / 256, 256>>>(cov);
    k_prepE<<<TOKENS / 8, 256>>>(eps, x, loc, out);   // 8 warps/block, 1 warp/token
    k_gemm<<<(TOKENS / BM) * JTILES, NT, SMEM_BYTES>>>(x, out);
}

// round 16
// speedup vs baseline: 1.0055x; 1.0055x over previous
#include <cuda_runtime.h>
#include <cuda_bf16.h>
#include <stdint.h>

// Problem constants
#define IN_F   64
#define OUT_F  32
#define NDIM   2080               // IN_F*OUT_F + OUT_F
#define TOKENS 16384              // B*S = 8*2048
#define MPAD   2176               // 17 * 128 (padded m-dim)
#define NTRI   (NDIM*(NDIM-1)/2)  // 2,162,160

// GEMM tiling
#define BM 128
#define BN 128
#define BK 32
#define NT 512                    // 16 warps: 4x4 warp grid, warp tile 32x32
#define JTILES 17                 // ceil(2080/128)

// Scratch (device globals: allocation-free at runtime)
__device__ __nv_bfloat16 g_E[(size_t)TOKENS * NDIM];  // eps in bf16, row-major [t][n]
__device__ __nv_bfloat16 g_A[(size_t)MPAD * NDIM];    // strict-lower cov in bf16, [m][n], diag=0, padded rows zero
__device__ float         g_d[NDIM];                   // exp(0.5*logvar)

// ---------------------------------------------------------------------------
// prep: diag scale
// ---------------------------------------------------------------------------
__global__ void k_scale(const float* __restrict__ logvar) {
    int i = blockIdx.x * blockDim.x + threadIdx.x;
    if (i < NDIM) g_d[i] = expf(0.5f * logvar[i]);
}

// ---------------------------------------------------------------------------
// prep: A matrix (strictly lower triangular cov, bf16, zero elsewhere)
// tril_indices(n,-1) row-major: index(m,n) = m*(m-1)/2 + n   (n < m)
// ---------------------------------------------------------------------------
__global__ void k_prepA(const float* __restrict__ cov) {
    int idx = blockIdx.x * blockDim.x + threadIdx.x;
    if (idx >= MPAD * NDIM) return;
    int m = idx / NDIM;
    int n = idx - m * NDIM;
    float v = 0.0f;
    if (m < NDIM && n < m) v = cov[m * (m - 1) / 2 + n];
    g_A[idx] = __float2bfloat16(v);
}

// ---------------------------------------------------------------------------
// prep: eps -> bf16, and exact fp32 base term written to out:
//   y_base[t,k] = loc[k] + d[k]*eps[t,k]
//              + sum_h x[t,h] * ( loc[32+32h+k] + d[32+32h+k]*eps[t,32+32h+k] )
// One warp per token; lane = k. Iteration i reads n = 32*i + lane:
//   i==0  -> bias term, i>=1 -> h = i-1 term. 65 iterations cover all 2080 n.
// ---------------------------------------------------------------------------
__global__ void k_prepE(const float* __restrict__ eps, const float* __restrict__ x,
                        const float* __restrict__ loc, float* __restrict__ out) {
    int warp = threadIdx.x >> 5;
    int lane = threadIdx.x & 31;
    int t = blockIdx.x * (blockDim.x >> 5) + warp;
    if (t >= TOKENS) return;

    const float* er = eps + (size_t)t * NDIM;
    __nv_bfloat16* eb = g_E + (size_t)t * NDIM;
    const float* xr = x + t * IN_F;

    float acc = 0.0f;
    for (int i = 0; i < 65; ++i) {
        int n = i * 32 + lane;
        float ep = er[n];
        eb[n] = __float2bfloat16(ep);
        float wv = loc[n] + g_d[n] * ep;
        acc = (i == 0) ? wv : fmaf(xr[i - 1], wv, acc);
    }
    out[t * OUT_F + lane] = acc;
}

// ---------------------------------------------------------------------------
// GEMM + fused epilogue
// ---------------------------------------------------------------------------
__device__ __forceinline__ void cpasync16(uint32_t d, const void* s) {
    asm volatile("cp.async.cg.shared.global [%0], [%1], 16;" :: "r"(d), "l"(s));
}
__device__ __forceinline__ void ldsm_x4(uint32_t& r0, uint32_t& r1, uint32_t& r2, uint32_t& r3, uint32_t a) {
    asm volatile("ldmatrix.sync.aligned.m8n8.x4.shared.b16 {%0,%1,%2,%3}, [%4];"
                 : "=r"(r0), "=r"(r1), "=r"(r2), "=r"(r3) : "r"(a));
}
__device__ __forceinline__ void ldsm_x2(uint32_t& r0, uint32_t& r1, uint32_t a) {
    asm volatile("ldmatrix.sync.aligned.m8n8.x2.shared.b16 {%0,%1}, [%2];"
                 : "=r"(r0), "=r"(r1) : "r"(a));
}
__device__ __forceinline__ void mma16816(float* c, const uint32_t* a, const uint32_t* b) {
    asm volatile("mma.sync.aligned.m16n8k16.row.col.f32.bf16.bf16.f32 "
                 "{%0,%1,%2,%3}, {%4,%5,%6,%7}, {%8,%9}, {%0,%1,%2,%3};"
                 : "+f"(c[0]), "+f"(c[1]), "+f"(c[2]), "+f"(c[3])
                 : "r"(a[0]), "r"(a[1]), "r"(a[2]), "r"(a[3]), "r"(b[0]), "r"(b[1]));
}

// smem layout (dynamic):
//   [0,8192)      E tile stage 0  (128 rows x 64B, XOR-swizzled 16B chunks)
//   [8192,16384)  E tile stage 1
//   [16384,24576) A tile stage 0
//   [24576,32768) A tile stage 1
//   [32768, +128*33*4) y accumulator (pitch 33 floats to dodge bank conflicts)
#define SMEM_Y_OFF 32768
#define SMEM_BYTES (SMEM_Y_OFF + 128 * 33 * 4)

__global__ void __launch_bounds__(NT, 1) k_gemm(const float* __restrict__ x,
                                                float* __restrict__ out) {
    extern __shared__ char smem[];
    uint32_t su = (uint32_t)__cvta_generic_to_shared(smem);
    float* ys = (float*)(smem + SMEM_Y_OFF);

    int tid  = threadIdx.x;
    int lane = tid & 31;
    int warp = tid >> 5;
    int wr = warp >> 2;   // token 32-block within CTA (0..3)
    int wc = warp & 3;    // m-col 32-block within CTA (0..3)

    int bj       = blockIdx.x % JTILES;       // m-tile (bid order: j fastest -> eps L2 reuse)
    int tokTile  = blockIdx.x / JTILES;
    int tok_base = tokTile * BM;
    int arow_base = bj * BN;
    int Ksteps = min(65, 4 * (bj + 1));       // triangular: n < 128*(bj+1), BK=32

    // zero y accumulator
    for (int i = tid; i < 128 * 33; i += NT) ys[i] = 0.0f;

    float acc[2][4][4];
    #pragma unroll
    for (int a = 0; a < 2; ++a)
        #pragma unroll
        for (int b = 0; b < 4; ++b)
            #pragma unroll
            for (int r = 0; r < 4; ++r) acc[a][b][r] = 0.0f;

    // cp.async task: each thread owns one 16B chunk of E tile and one of A tile
    int rr0 = tid >> 2, cc0 = tid & 3;
    uint32_t swz = ((uint32_t)(cc0 ^ ((rr0 >> 1) & 3))) << 4;
    uint32_t edst = su + rr0 * 64 + swz;
    uint32_t adst = su + 16384 + rr0 * 64 + swz;
    const __nv_bfloat16* esrc = g_E + (size_t)(tok_base + rr0) * NDIM + cc0 * 8;
    const __nv_bfloat16* asrc = g_A + (size_t)(arow_base + rr0) * NDIM + cc0 * 8;

    auto issue = [&](int st, int ks) {
        cpasync16(edst + st * 8192, esrc + ks * 32);
        cpasync16(adst + st * 8192, asrc + ks * 32);
        asm volatile("cp.async.commit_group;");
    };

    issue(0, 0);
    for (int ks = 0; ks < Ksteps; ++ks) {
        if (ks + 1 < Ksteps) {
            issue((ks + 1) & 1, ks + 1);
            asm volatile("cp.async.wait_group 1;");
        } else {
            asm volatile("cp.async.wait_group 0;");
        }
        __syncthreads();

        int st = ks & 1;
        uint32_t eBase = su + st * 8192;
        uint32_t aBase = su + 16384 + st * 8192;

        #pragma unroll
        for (int s = 0; s < 2; ++s) {          // two k16 halves of BK=32
            uint32_t a[2][4], b[4][2];
            #pragma unroll
            for (int fm = 0; fm < 2; ++fm) {   // A operand = E tile (tokens x k)
                int row = 32 * wr + 16 * fm + (lane & 7) + ((lane >> 3) & 1) * 8;
                int ch = 2 * s + (lane >> 4);
                uint32_t ad = eBase + row * 64 + (((uint32_t)(ch ^ ((row >> 1) & 3))) << 4);
                ldsm_x4(a[fm][0], a[fm][1], a[fm][2], a[fm][3], ad);
            }
            #pragma unroll
            for (int fn = 0; fn < 4; ++fn) {   // B operand = A tile (m x k), col-major fit
                int row = 32 * wc + 8 * fn + (lane & 7);
                int ch = 2 * s + ((lane >> 3) & 1);
                uint32_t ad = aBase + row * 64 + (((uint32_t)(ch ^ ((row >> 1) & 3))) << 4);
                ldsm_x2(b[fn][0], b[fn][1], ad);
            }
            #pragma unroll
            for (int fm = 0; fm < 2; ++fm)
                #pragma unroll
                for (int fn = 0; fn < 4; ++fn)
                    mma16816(acc[fm][fn], a[fm], b[fn]);
        }
        __syncthreads();
    }

    // Fused epilogue: C[t,m] contributes to exactly one k
    //   m < 32      : k = m,            weight 1      (bias)
    //   m >= 32     : k = (m-32)&31,    weight x[t, (m-32)>>5]
    #pragma unroll
    for (int fm = 0; fm < 2; ++fm) {
        #pragma unroll
        for (int fn = 0; fn < 4; ++fn) {
            #pragma unroll
            for (int r = 0; r < 4; ++r) {
                int tl = 32 * wr + 16 * fm + (lane >> 2) + (r >> 1) * 8;
                int ml = 32 * wc + 8 * fn + (lane & 3) * 2 + (r & 1);
                int m = arow_base + ml;
                if (m < NDIM) {
                    float w;
                    int k;
                    if (m < OUT_F) { w = 1.0f; k = m; }
                    else {
                        int mm = m - OUT_F;
                        k = mm & 31;
                        w = x[(tok_base + tl) * IN_F + (mm >> 5)];
                    }
                    atomicAdd(&ys[tl * 33 + k], w * acc[fm][fn][r]);
                }
            }
        }
    }
    __syncthreads();

    for (int i = tid; i < BM * OUT_F; i += NT) {
        int tl = i >> 5, k = i & 31;
        atomicAdd(&out[(size_t)(tok_base + tl) * OUT_F + k], ys[tl * 33 + k]);
    }
}

// ---------------------------------------------------------------------------
// launch
// ---------------------------------------------------------------------------
extern "C" void kernel_launch(void* const* d_in, const int* in_sizes, int n_in,
                              void* d_out, int out_size) {
    const float *x = nullptr, *eps = nullptr, *loc = nullptr, *logvar = nullptr, *cov = nullptr;
    for (int i = 0; i < n_in; ++i) {
        int s = in_sizes[i];
        const float* p = (const float*)d_in[i];
        if (s == TOKENS * IN_F)      x = p;
        else if (s == TOKENS * NDIM) eps = p;
        else if (s == NTRI)          cov = p;
        else if (s == NDIM) { if (!loc) loc = p; else logvar = p; }  // dict order: loc, logvar
    }
    if (!x || !eps || !loc || !logvar || !cov) return;
    float* out = (float*)d_out;

    cudaFuncSetAttribute(k_gemm, cudaFuncAttributeMaxDynamicSharedMemorySize, SMEM_BYTES);

    k_scale<<<(NDIM + 255) / 256, 256>>>(logvar);
    k_prepA<<<(MPAD * NDIM + 255) / 256, 256>>>(cov);
    k_prepE<<<TOKENS / 8, 256>>>(eps, x, loc, out);   // 8 warps/block, 1 warp/token
    k_gemm<<<(TOKENS / BM) * JTILES, NT, SMEM_BYTES>>>(x, out);
}

// round 17
// speedup vs baseline: 1.0059x; 1.0003x over previous
#include <cuda_runtime.h>
#include <cuda_bf16.h>
#include <stdint.h>

// Problem constants
#define IN_F   64
#define OUT_F  32
#define NDIM   2080               // IN_F*OUT_F + OUT_F
#define TOKENS 16384              // B*S = 8*2048
#define MPAD   2176               // 17 * 128 (padded m-dim)
#define NTRI   (NDIM*(NDIM-1)/2)  // 2,162,160

// GEMM tiling
#define BM 128
#define BN 128
#define BK 32
#define NT 512                    // 16 warps: 4x4 warp grid, warp tile 32x32
#define JTILES 17                 // ceil(2080/128)

// Scratch (device globals: allocation-free at runtime)
__device__ __nv_bfloat16 g_E[(size_t)TOKENS * NDIM];  // eps in bf16, row-major [t][n]
__device__ __nv_bfloat16 g_A[(size_t)MPAD * NDIM];    // strict-lower cov in bf16, [m][n], diag=0, padded rows zero
__device__ float         g_d[NDIM];                   // exp(0.5*logvar)

// ---------------------------------------------------------------------------
// prep: diag scale
// ---------------------------------------------------------------------------
__global__ void k_scale(const float* __restrict__ logvar) {
    int i = blockIdx.x * blockDim.x + threadIdx.x;
    if (i < NDIM) g_d[i] = expf(0.5f * logvar[i]);
}

// ---------------------------------------------------------------------------
// prep: A matrix (strictly lower triangular cov, bf16, zero elsewhere)
// tril_indices(n,-1) row-major: index(m,n) = m*(m-1)/2 + n   (n < m)
// ---------------------------------------------------------------------------
__global__ void k_prepA(const float* __restrict__ cov) {
    int idx = blockIdx.x * blockDim.x + threadIdx.x;
    if (idx >= MPAD * NDIM) return;
    int m = idx / NDIM;
    int n = idx - m * NDIM;
    float v = 0.0f;
    if (m < NDIM && n < m) v = cov[m * (m - 1) / 2 + n];
    g_A[idx] = __float2bfloat16(v);
}

// ---------------------------------------------------------------------------
// prep: eps -> bf16, and exact fp32 base term written to out:
//   y_base[t,k] = loc[k] + d[k]*eps[t,k]
//              + sum_h x[t,h] * ( loc[32+32h+k] + d[32+32h+k]*eps[t,32+32h+k] )
// One warp per token; lane = k. Iteration i reads n = 32*i + lane:
//   i==0  -> bias term, i>=1 -> h = i-1 term. 65 iterations cover all 2080 n.
// ---------------------------------------------------------------------------
__global__ void k_prepE(const float* __restrict__ eps, const float* __restrict__ x,
                        const float* __restrict__ loc, float* __restrict__ out) {
    int warp = threadIdx.x >> 5;
    int lane = threadIdx.x & 31;
    int t = blockIdx.x * (blockDim.x >> 5) + warp;
    if (t >= TOKENS) return;

    const float* er = eps + (size_t)t * NDIM;
    __nv_bfloat16* eb = g_E + (size_t)t * NDIM;
    const float* xr = x + t * IN_F;

    float acc = 0.0f;
    for (int i = 0; i < 65; ++i) {
        int n = i * 32 + lane;
        float ep = er[n];
        eb[n] = __float2bfloat16(ep);
        float wv = loc[n] + g_d[n] * ep;
        acc = (i == 0) ? wv : fmaf(xr[i - 1], wv, acc);
    }
    out[t * OUT_F + lane] = acc;
}

// ---------------------------------------------------------------------------
// GEMM + fused epilogue
// ---------------------------------------------------------------------------
__device__ __forceinline__ void cpasync16(uint32_t d, const void* s) {
    asm volatile("cp.async.cg.shared.global [%0], [%1], 16;" :: "r"(d), "l"(s));
}
__device__ __forceinline__ void ldsm_x4(uint32_t& r0, uint32_t& r1, uint32_t& r2, uint32_t& r3, uint32_t a) {
    asm volatile("ldmatrix.sync.aligned.m8n8.x4.shared.b16 {%0,%1,%2,%3}, [%4];"
                 : "=r"(r0), "=r"(r1), "=r"(r2), "=r"(r3) : "r"(a));
}
__device__ __forceinline__ void ldsm_x2(uint32_t& r0, uint32_t& r1, uint32_t a) {
    asm volatile("ldmatrix.sync.aligned.m8n8.x2.shared.b16 {%0,%1}, [%2];"
                 : "=r"(r0), "=r"(r1) : "r"(a));
}
__device__ __forceinline__ void mma16816(float* c, const uint32_t* a, const uint32_t* b) {
    asm volatile("mma.sync.aligned.m16n8k16.row.col.f32.bf16.bf16.f32 "
                 "{%0,%1,%2,%3}, {%4,%5,%6,%7}, {%8,%9}, {%0,%1,%2,%3};"
                 : "+f"(c[0]), "+f"(c[1]), "+f"(c[2]), "+f"(c[3])
                 : "r"(a[0]), "r"(a[1]), "r"(a[2]), "r"(a[3]), "r"(b[0]), "r"(b[1]));
}

// smem layout (dynamic):
//   [0,8192)      E tile stage 0  (128 rows x 64B, XOR-swizzled 16B chunks)
//   [8192,16384)  E tile stage 1
//   [16384,24576) A tile stage 0
//   [24576,32768) A tile stage 1
//   [32768, +128*33*4) y accumulator (pitch 33 floats to dodge bank conflicts)
#define SMEM_Y_OFF 32768
#define SMEM_BYTES (SMEM_Y_OFF + 128 * 33 * 4)

__global__ void __launch_bounds__(NT, 1) k_gemm(const float* __restrict__ x,
                                                float* __restrict__ out) {
    extern __shared__ char smem[];
    uint32_t su = (uint32_t)__cvta_generic_to_shared(smem);
    float* ys = (float*)(smem + SMEM_Y_OFF);

    int tid  = threadIdx.x;
    int lane = tid & 31;
    int warp = tid >> 5;
    int wr = warp >> 2;   // token 32-block within CTA (0..3)
    int wc = warp & 3;    // m-col 32-block within CTA (0..3)

    int bj       = blockIdx.x % JTILES;       // m-tile (bid order: j fastest -> eps L2 reuse)
    int tokTile  = blockIdx.x / JTILES;
    int tok_base = tokTile * BM;
    int arow_base = bj * BN;
    int Ksteps = min(65, 4 * (bj + 1));       // triangular: n < 128*(bj+1), BK=32

    // zero y accumulator
    for (int i = tid; i < 128 * 33; i += NT) ys[i] = 0.0f;

    float acc[2][4][4];
    #pragma unroll
    for (int a = 0; a < 2; ++a)
        #pragma unroll
        for (int b = 0; b < 4; ++b)
            #pragma unroll
            for (int r = 0; r < 4; ++r) acc[a][b][r] = 0.0f;

    // cp.async task: each thread owns one 16B chunk of E tile and one of A tile
    int rr0 = tid >> 2, cc0 = tid & 3;
    uint32_t swz = ((uint32_t)(cc0 ^ ((rr0 >> 1) & 3))) << 4;
    uint32_t edst = su + rr0 * 64 + swz;
    uint32_t adst = su + 16384 + rr0 * 64 + swz;
    const __nv_bfloat16* esrc = g_E + (size_t)(tok_base + rr0) * NDIM + cc0 * 8;
    const __nv_bfloat16* asrc = g_A + (size_t)(arow_base + rr0) * NDIM + cc0 * 8;

    auto issue = [&](int st, int ks) {
        cpasync16(edst + st * 8192, esrc + ks * 32);
        cpasync16(adst + st * 8192, asrc + ks * 32);
        asm volatile("cp.async.commit_group;");
    };

    issue(0, 0);
    for (int ks = 0; ks < Ksteps; ++ks) {
        if (ks + 1 < Ksteps) {
            issue((ks + 1) & 1, ks + 1);
            asm volatile("cp.async.wait_group 1;");
        } else {
            asm volatile("cp.async.wait_group 0;");
        }
        __syncthreads();

        int st = ks & 1;
        uint32_t eBase = su + st * 8192;
        uint32_t aBase = su + 16384 + st * 8192;

        #pragma unroll
        for (int s = 0; s < 2; ++s) {          // two k16 halves of BK=32
            uint32_t a[2][4], b[4][2];
            #pragma unroll
            for (int fm = 0; fm < 2; ++fm) {   // A operand = E tile (tokens x k)
                int row = 32 * wr + 16 * fm + (lane & 7) + ((lane >> 3) & 1) * 8;
                int ch = 2 * s + (lane >> 4);
                uint32_t ad = eBase + row * 64 + (((uint32_t)(ch ^ ((row >> 1) & 3))) << 4);
                ldsm_x4(a[fm][0], a[fm][1], a[fm][2], a[fm][3], ad);
            }
            #pragma unroll
            for (int fn = 0; fn < 4; ++fn) {   // B operand = A tile (m x k), col-major fit
                int row = 32 * wc + 8 * fn + (lane & 7);
                int ch = 2 * s + ((lane >> 3) & 1);
                uint32_t ad = aBase + row * 64 + (((uint32_t)(ch ^ ((row >> 1) & 3))) << 4);
                ldsm_x2(b[fn][0], b[fn][1], ad);
            }
            #pragma unroll
            for (int fm = 0; fm < 2; ++fm)
                #pragma unroll
                for (int fn = 0; fn < 4; ++fn)
                    mma16816(acc[fm][fn], a[fm], b[fn]);
        }
        __syncthreads();
    }

    // Fused epilogue: C[t,m] contributes to exactly one k
    //   m < 32      : k = m,            weight 1      (bias)
    //   m >= 32     : k = (m-32)&31,    weight x[t, (m-32)>>5]
    #pragma unroll
    for (int fm = 0; fm < 2; ++fm) {
        #pragma unroll
        for (int fn = 0; fn < 4; ++fn) {
            #pragma unroll
            for (int r = 0; r < 4; ++r) {
                int tl = 32 * wr + 16 * fm + (lane >> 2) + (r >> 1) * 8;
                int ml = 32 * wc + 8 * fn + (lane & 3) * 2 + (r & 1);
                int m = arow_base + ml;
                if (m < NDIM) {
                    float w;
                    int k;
                    if (m < OUT_F) { w = 1.0f; k = m; }
                    else {
                        int mm = m - OUT_F;
                        k = mm & 31;
                        w = x[(tok_base + tl) * IN_F + (mm >> 5)];
                    }
                    atomicAdd(&ys[tl * 33 + k], w * acc[fm][fn][r]);
                }
            }
        }
    }
    __syncthreads();

    for (int i = tid; i < BM * OUT_F; i += NT) {
        int tl = i >> 5, k = i & 31;
        atomicAdd(&out[(size_t)(tok_base + tl) * OUT_F + k], ys[tl * 33 + k]);
    }
}

// ---------------------------------------------------------------------------
// launch
// ---------------------------------------------------------------------------
extern "C" void kernel_launch(void* const* d_in, const int* in_sizes, int n_in,
                              void* d_out, int out_size) {
    const float *x = nullptr, *eps = nullptr, *loc = nullptr, *logvar = nullptr, *cov = nullptr;
    for (int i = 0; i < n_in; ++i) {
        int s = in_sizes[i];
        const float* p = (const float*)d_in[i];
        if (s == TOKENS * IN_F)      x = p;
        else if (s == TOKENS * NDIM) eps = p;
        else if (s == NTRI)          cov = p;
        else if (s == NDIM) { if (!loc) loc = p; else logvar = p; }  // dict order: loc, logvar
    }
    if (!x || !eps || !loc || !logvar || !cov) return;
    float* out = (float*)d_out;

    cudaFuncSetAttribute(k_gemm, cudaFuncAttributeMaxDynamicSharedMemorySize, SMEM_BYTES);

    k_scale<<<(NDIM + 255) / 256, 256>>>(logvar);
    k_prepA<<<(MPAD * NDIM + 255) / 256, 256>>>(cov);
    k_prepE<<<TOKENS / 8, 256>>>(eps, x, loc, out);   // 8 warps/block, 1 warp/token
    k_gemm<<<(TOKENS / BM) * JTILES, NT, SMEM_BYTES>>>(x, out);
}